// round 1
// baseline (speedup 1.0000x reference)
#include <cuda_runtime.h>
#include <math.h>

// Problem constants (fixed shapes)
#define Bn    128   // batch
#define Tn    64    // timesteps
#define DEn   768   // encoder dim
#define Un    256   // LSTM units
#define Vn    48    // label vocab
#define Sn    192   // decode steps = 3 * T
#define NBLK  128   // persistent blocks (<=148 SMs -> all co-resident)
#define NTHR  256

// ---------------- device scratch (static: no allocation) ----------------
// proj[j][b][t][8] : per-unit-pair packed projection of inputs @ W[256:,:]
__device__ float    g_proj[(size_t)NBLK * Bn * Tn * 8];   // 33.5 MB
// embP[j][v][8] : embed @ W[:256,:] + bias, packed per unit-pair
__device__ float    g_embP[NBLK * Vn * 8];
// wP[j][k][8]   : Uw packed per unit-pair (k-major, 8 gate-weights per k)
__device__ float    g_wP[NBLK * Un * 8];
__device__ float    g_h[2][Un * Bn];   // hT ping-pong, [k][b] layout
__device__ float    g_c[2][Un * Bn];   // cT ping-pong, [u][b] layout
__device__ int      g_tgt[Bn];
__device__ int      g_adj[Bn];
__device__ int      g_ts[Bn];
__device__ unsigned g_bar[512];        // monotonic barrier slots (reset by k_reset)

// ---------------- reset / init ----------------
__global__ void k_reset(const int* __restrict__ word_ids) {
    int idx = blockIdx.x * blockDim.x + threadIdx.x;
    int stride = gridDim.x * blockDim.x;
    for (int i = idx; i < 512; i += stride) g_bar[i] = 0u;
    float* hflat = (float*)g_h;
    float* cflat = (float*)g_c;
    for (int i = idx; i < 2 * Un * Bn; i += stride) { hflat[i] = 0.f; cflat[i] = 0.f; }
    if (idx < Bn) {
        g_tgt[idx] = 1;  // BOS
        g_adj[idx] = 0;  // hai=0 < timesteps always at start
        int c = 0;
        for (int t = 0; t < Tn; t++) c += (word_ids[idx * Tn + t] != 0);
        g_ts[idx] = c;
    }
}

// ---------------- pack embed @ W[:256,:] + bias ----------------
__global__ void k_embpack(const float* __restrict__ embed,
                          const float* __restrict__ W,
                          const float* __restrict__ bias) {
    int t = blockIdx.x;
    int col = blockIdx.y * 256 + threadIdx.x;
    float acc = bias[col];
    for (int e = 0; e < 256; e++)
        acc += embed[t * 256 + e] * W[e * 1024 + col];
    int u = col & 255, g = col >> 8;
    g_embP[(((u >> 1) * Vn) + t) * 8 + (u & 1) * 4 + g] = acc;
}

// ---------------- pack Uw ----------------
__global__ void k_wpack(const float* __restrict__ Uw) {
    int idx = blockIdx.x * blockDim.x + threadIdx.x;  // 0..262143
    int j = idx >> 11;
    int r = idx & 2047;
    int k = r >> 3;
    int q = r & 7;
    int ul = q >> 2, g = q & 3;
    int col = g * 256 + j * 2 + ul;
    g_wP[idx] = Uw[k * 1024 + col];
}

// ---------------- proj GEMM: [8192,768] @ W[256:1024, :1024] -> packed ----------------
__global__ void __launch_bounds__(256) k_proj(const float* __restrict__ A,
                                              const float* __restrict__ W) {
    __shared__ float As[64 * 16];
    __shared__ float Bs[16 * 64];
    int row0 = blockIdx.y * 64, col0 = blockIdx.x * 64;
    int tid = threadIdx.x;
    int tr = tid >> 4, tc = tid & 15;
    float acc[4][4] = {};
    int lr = tid >> 2, lk = (tid & 3) * 4;      // A tile loader
    int lkb = tid >> 4, lcb = (tid & 15) * 4;   // B tile loader
    for (int k0 = 0; k0 < 768; k0 += 16) {
        float4 av = *(const float4*)&A[(size_t)(row0 + lr) * 768 + k0 + lk];
        *(float4*)&As[lr * 16 + lk] = av;
        float4 bv = *(const float4*)&W[(size_t)(256 + k0 + lkb) * 1024 + col0 + lcb];
        *(float4*)&Bs[lkb * 64 + lcb] = bv;
        __syncthreads();
#pragma unroll
        for (int kk = 0; kk < 16; kk++) {
            float a[4];
#pragma unroll
            for (int i = 0; i < 4; i++) a[i] = As[(tr * 4 + i) * 16 + kk];
            float4 b4 = *(float4*)&Bs[kk * 64 + tc * 4];
            float b[4] = {b4.x, b4.y, b4.z, b4.w};
#pragma unroll
            for (int i = 0; i < 4; i++)
#pragma unroll
                for (int c = 0; c < 4; c++) acc[i][c] += a[i] * b[c];
        }
        __syncthreads();
    }
#pragma unroll
    for (int i = 0; i < 4; i++) {
        int row = row0 + tr * 4 + i;
        int bb = row >> 6, tt = row & 63;
#pragma unroll
        for (int c = 0; c < 4; c++) {
            int col = col0 + tc * 4 + c;
            int u = col & 255, g = col >> 8, jb = u >> 1, ul = u & 1;
            g_proj[((((size_t)jb * Bn) + bb) * Tn + tt) * 8 + ul * 4 + g] = acc[i][c];
        }
    }
}

// ---------------- persistent decode loop ----------------
__device__ __forceinline__ float sigm(float x) { return 1.0f / (1.0f + expf(-x)); }

__device__ __forceinline__ void gbar(int slot) {
    __threadfence();            // make this thread's global stores visible at GPU scope
    __syncthreads();            // all threads' fences done before leader arrives
    if (threadIdx.x == 0) {
        atomicAdd(&g_bar[slot], 1u);
        volatile unsigned* p = &g_bar[slot];
        while (*p < (unsigned)NBLK) {}
    }
    __syncthreads();
}

__global__ void __launch_bounds__(NTHR, 1) k_loop(const float* __restrict__ Wo,
                                                  const float* __restrict__ bo,
                                                  float* __restrict__ out) {
    __shared__ float wsm[Un * 8];   // 8 KB: this block's Uw slice, resident all 192 steps
    __shared__ float psum[Bn * 8];  // split-K partials from half 1
    __shared__ float lsm[256];
    __shared__ float fsm[Vn];
    int j = blockIdx.x, tid = threadIdx.x;

    for (int i = tid; i < Un * 8; i += NTHR) wsm[i] = g_wP[j * Un * 8 + i];

    int hai = 0, reps = 0, ts = 0;
    if (tid == 0) ts = g_ts[j];
    __syncthreads();

    int cur = 0;
    int half = tid >> 7, b = tid & 127;
    int kg = tid >> 6, v = tid & 63;

    for (int s = 0; s < Sn; s++) {
        const float* hIn = g_h[cur];
        float* hOut = g_h[cur ^ 1];
        const float* cIn = g_c[cur];
        float* cOut = g_c[cur ^ 1];

        // ---- z phase: block j computes gates for units {2j, 2j+1}, all 128 b ----
        int tgt = __ldcg(&g_tgt[b]);
        int adj = __ldcg(&g_adj[b]);
        float acc[8];
#pragma unroll
        for (int q = 0; q < 8; q++) acc[q] = 0.f;
        const float* hp = hIn + (size_t)half * 128 * Bn + b;
        const float* wp = wsm + half * 128 * 8;
#pragma unroll 8
        for (int kk = 0; kk < 128; kk++) {
            float hk = __ldcg(hp + kk * Bn);
#pragma unroll
            for (int q = 0; q < 8; q++) acc[q] += hk * wp[kk * 8 + q];
        }
        if (half == 1) {
#pragma unroll
            for (int q = 0; q < 8; q++) psum[b * 8 + q] = acc[q];
        }
        __syncthreads();
        if (half == 0) {
            const float* ep = &g_embP[(j * Vn + tgt) * 8];
            const float* pp = &g_proj[((((size_t)j * Bn) + b) * Tn + adj) * 8];
#pragma unroll
            for (int ul = 0; ul < 2; ul++) {
                float zi = acc[ul * 4 + 0] + psum[b * 8 + ul * 4 + 0] + ep[ul * 4 + 0] + pp[ul * 4 + 0];
                float zf = acc[ul * 4 + 1] + psum[b * 8 + ul * 4 + 1] + ep[ul * 4 + 1] + pp[ul * 4 + 1];
                float zg = acc[ul * 4 + 2] + psum[b * 8 + ul * 4 + 2] + ep[ul * 4 + 2] + pp[ul * 4 + 2];
                float zo = acc[ul * 4 + 3] + psum[b * 8 + ul * 4 + 3] + ep[ul * 4 + 3] + pp[ul * 4 + 3];
                int u = j * 2 + ul;
                float cold = cIn[u * Bn + b];
                float c2 = sigm(zf) * cold + sigm(zi) * tanhf(zg);
                float h2 = sigm(zo) * tanhf(c2);
                cOut[u * Bn + b] = c2;
                hOut[u * Bn + b] = h2;
            }
        }
        gbar(2 * s);  // h2 complete everywhere

        // ---- logits + argmax + control for batch row b = j ----
        float p = 0.f;
        if (v < Vn) {
            const float* hc = hOut + (size_t)kg * 64 * Bn + j;
            const float* wv = Wo + kg * 64 * Vn + v;
#pragma unroll 8
            for (int i = 0; i < 64; i++) p += __ldcg(hc + i * Bn) * wv[i * Vn];
        }
        lsm[tid] = p;
        __syncthreads();
        if (tid < Vn)
            fsm[tid] = lsm[tid] + lsm[64 + tid] + lsm[128 + tid] + lsm[192 + tid] + bo[tid];
        __syncthreads();
        if (tid == 0) {
            float bv = fsm[0];
            int bi = 0;
            for (int v2 = 1; v2 < Vn; v2++) {
                float x = fsm[v2];
                if (x > bv) { bv = x; bi = v2; }
            }
            int preds = bi;
            if (reps >= 3) preds = 2;                 // EOW override (reps stays 0 per reference)
            int res = (hai == ts) ? 0 : preds;        // BATCH_PAD mask, pre-update hai
            out[j * Sn + s] = (float)res;
            int inc = (preds == 2 && hai < ts) ? 1 : 0;
            hai += inc;
            if (inc) reps = 0;
            g_tgt[j] = preds;
            g_adj[j] = (hai < ts) ? hai : hai - 1;
        }
        gbar(2 * s + 1);  // targets/adj published
        cur ^= 1;
    }
}

// ---------------- launch ----------------
extern "C" void kernel_launch(void* const* d_in, const int* in_sizes, int n_in,
                              void* d_out, int out_size) {
    (void)in_sizes; (void)n_in; (void)out_size;
    const float* inputs   = (const float*)d_in[0];
    const int*   word_ids = (const int*)d_in[1];
    const float* embed    = (const float*)d_in[2];
    const float* W        = (const float*)d_in[3];
    const float* Uw       = (const float*)d_in[4];
    const float* bias     = (const float*)d_in[5];
    const float* Wo       = (const float*)d_in[6];
    const float* bo       = (const float*)d_in[7];
    float* out = (float*)d_out;

    k_reset<<<64, 256>>>(word_ids);
    k_embpack<<<dim3(48, 4), 256>>>(embed, W, bias);
    k_wpack<<<1024, 256>>>(Uw);
    k_proj<<<dim3(16, 128), 256>>>(inputs, W);
    k_loop<<<NBLK, NTHR>>>(Wo, bo, out);
}